// round 1
// baseline (speedup 1.0000x reference)
#include <cuda_runtime.h>
#include <cuda_bf16.h>

// Problem constants
#define KC   1024      // codebook size
#define DD   256       // feature dim (C)
#define BB   32        // batch
#define HWD  1024      // H*W
#define NPIX (BB*HWD)  // 32768 pixels
#define CHW  (DD*HWD)  // per-batch stride

// Scratch (allocation-free: __device__ globals)
__device__ float g_emb_t[DD * KC];   // emb transposed: [c][k]
__device__ float g_hn[KC];           // 0.5*||e_k||^2
__device__ int   g_argmin[NPIX];

// ---------------------------------------------------------------------------
// Packed f32x2 helpers (Blackwell FFMA2 — ptxas won't auto-fuse; PTX only)
// ---------------------------------------------------------------------------
__device__ __forceinline__ unsigned long long pack2(float v) {
    unsigned long long r;
    asm("mov.b64 %0, {%1, %1};" : "=l"(r) : "f"(v));
    return r;
}
__device__ __forceinline__ void ffma2(unsigned long long& d,
                                      unsigned long long a,
                                      unsigned long long b) {
    asm("fma.rn.f32x2 %0, %1, %2, %0;" : "+l"(d) : "l"(a), "l"(b));
}
__device__ __forceinline__ void unpack2(unsigned long long v, float& lo, float& hi) {
    asm("mov.b64 {%0, %1}, %2;" : "=f"(lo), "=f"(hi) : "l"(v));
}

// ---------------------------------------------------------------------------
// Prep 1: transpose emb (K,D) -> emb_t (D,K)
// grid (K/32, D/32), block (32, 8)
// ---------------------------------------------------------------------------
__global__ void vq_transpose_kernel(const float* __restrict__ emb) {
    __shared__ float tile[32][33];
    int k0 = blockIdx.x * 32;
    int c0 = blockIdx.y * 32;
    int tx = threadIdx.x, ty = threadIdx.y;
    #pragma unroll
    for (int j = 0; j < 4; j++) {
        int row = ty + j * 8;                       // local k
        tile[row][tx] = emb[(k0 + row) * DD + c0 + tx];
    }
    __syncthreads();
    #pragma unroll
    for (int j = 0; j < 4; j++) {
        int row = ty + j * 8;                       // local c
        g_emb_t[(c0 + row) * KC + k0 + tx] = tile[tx][row];
    }
}

// ---------------------------------------------------------------------------
// Prep 2: hn[k] = 0.5 * sum_c emb[k][c]^2
// ---------------------------------------------------------------------------
__global__ void vq_hn_kernel(const float* __restrict__ emb) {
    int k = blockIdx.x * blockDim.x + threadIdx.x;
    if (k >= KC) return;
    const float4* row = (const float4*)(emb + k * DD);
    float s = 0.f;
    #pragma unroll 8
    for (int i = 0; i < DD / 4; i++) {
        float4 v = row[i];
        s += v.x * v.x + v.y * v.y + v.z * v.z + v.w * v.w;
    }
    g_hn[k] = 0.5f * s;
}

// ---------------------------------------------------------------------------
// Main: per-pixel argmax_k (x.e_k - 0.5||e_k||^2)
// Block tile: 64 pixels x 128 codes, loop 8 code tiles, C chunked by 16.
// 256 threads as 16(tx: codes) x 16(ty: pixels); thread tile 4 pixels x 8 codes
// held as 16 f32x2 accumulators.
// ---------------------------------------------------------------------------
__global__ __launch_bounds__(256) void vq_main_kernel(const float* __restrict__ x) {
    __shared__ __align__(16) float As[16][64];    // [cc][pixel]
    __shared__ __align__(16) float Bs[16][128];   // [cc][code]
    __shared__ float redS[64][16];
    __shared__ int   redI[64][16];

    int tile = blockIdx.x;            // 512 tiles
    int b    = tile >> 4;             // 16 tiles per batch image
    int hw0  = (tile & 15) << 6;      // *64
    const float* xb = x + (size_t)b * CHW + hw0;

    int t  = threadIdx.x;
    int tx = t & 15;
    int ty = t >> 4;

    float best[4];
    int   bidx[4];
    #pragma unroll
    for (int i = 0; i < 4; i++) { best[i] = -3.0e38f; bidx[i] = 0; }

    for (int kt = 0; kt < 8; kt++) {
        int k0 = kt << 7;
        unsigned long long acc[4][4];
        #pragma unroll
        for (int i = 0; i < 4; i++)
            #pragma unroll
            for (int j = 0; j < 4; j++) acc[i][j] = 0ULL;

        for (int c0 = 0; c0 < DD; c0 += 16) {
            // stage x tile: 1024 floats, coalesced, conflict-free
            #pragma unroll
            for (int i = 0; i < 4; i++) {
                int e = t + i * 256;
                As[e >> 6][e & 63] = xb[(size_t)(c0 + (e >> 6)) * HWD + (e & 63)];
            }
            // stage emb_t tile: 2048 floats, coalesced, conflict-free
            #pragma unroll
            for (int i = 0; i < 8; i++) {
                int e = t + i * 256;
                Bs[e >> 7][e & 127] = g_emb_t[(size_t)(c0 + (e >> 7)) * KC + k0 + (e & 127)];
            }
            __syncthreads();

            #pragma unroll
            for (int cc = 0; cc < 16; cc++) {
                float4 av = *(const float4*)(&As[cc][ty << 2]);
                unsigned long long a2[4] = { pack2(av.x), pack2(av.y),
                                             pack2(av.z), pack2(av.w) };
                ulonglong2 bA = *(const ulonglong2*)(&Bs[cc][tx << 3]);
                ulonglong2 bB = *(const ulonglong2*)(&Bs[cc][(tx << 3) + 4]);
                unsigned long long b2[4] = { bA.x, bA.y, bB.x, bB.y };
                #pragma unroll
                for (int i = 0; i < 4; i++)
                    #pragma unroll
                    for (int j = 0; j < 4; j++)
                        ffma2(acc[i][j], a2[i], b2[j]);
            }
            __syncthreads();
        }

        // fold this code tile into the running per-pixel best
        int kbase = k0 + (tx << 3);
        #pragma unroll
        for (int j = 0; j < 4; j++) {
            float hlo = __ldg(&g_hn[kbase + 2 * j]);
            float hhi = __ldg(&g_hn[kbase + 2 * j + 1]);
            #pragma unroll
            for (int i = 0; i < 4; i++) {
                float lo, hi;
                unpack2(acc[i][j], lo, hi);
                float slo = lo - hlo;
                float shi = hi - hhi;
                if (slo > best[i]) { best[i] = slo; bidx[i] = kbase + 2 * j; }
                if (shi > best[i]) { best[i] = shi; bidx[i] = kbase + 2 * j + 1; }
            }
        }
    }

    // cross-tx reduction (16 candidates per pixel)
    #pragma unroll
    for (int i = 0; i < 4; i++) {
        redS[(ty << 2) + i][tx] = best[i];
        redI[(ty << 2) + i][tx] = bidx[i];
    }
    __syncthreads();
    if (t < 64) {
        float bs = -3.0e38f;
        int bi = KC;
        #pragma unroll
        for (int q = 0; q < 16; q++) {
            float s = redS[t][q];
            int   i = redI[t][q];
            if (s > bs || (s == bs && i < bi)) { bs = s; bi = i; }
        }
        g_argmin[b * HWD + hw0 + t] = bi;
    }
}

// ---------------------------------------------------------------------------
// Epilogue: z_q[b][c][hw] = emb[argmin[b][hw]][c]   (smem-staged transpose)
// grid: 32 * 8 blocks; each block: one b, 128 pixels, loop c in chunks of 32.
// ---------------------------------------------------------------------------
__global__ __launch_bounds__(256) void vq_zq_kernel(const float* __restrict__ emb,
                                                    float* __restrict__ out_zq) {
    __shared__ int   sidx[128];
    __shared__ float zq[32][133];   // pad -> conflict-free gather stores

    int blk = blockIdx.x;           // 256 blocks
    int b   = blk >> 3;
    int hw0 = (blk & 7) << 7;       // *128

    int t    = threadIdx.x;
    int lane = t & 31;
    int w    = t >> 5;              // 8 warps

    if (t < 128) sidx[t] = g_argmin[b * HWD + hw0 + t];
    __syncthreads();

    float* outb = out_zq + (size_t)b * CHW + hw0;

    for (int c0 = 0; c0 < DD; c0 += 32) {
        // gather: one warp per pixel row, 32 consecutive c per lane (coalesced)
        for (int p = w; p < 128; p += 8) {
            int id = sidx[p];
            zq[lane][p] = emb[(size_t)id * DD + c0 + lane];
        }
        __syncthreads();
        // write: 128-consecutive-hw coalesced stores
        int p  = t & 127;
        int c1 = t >> 7;            // 0..1
        #pragma unroll
        for (int r = 0; r < 16; r++) {
            int cc = c1 + r * 2;
            outb[(size_t)(c0 + cc) * HWD + p] = zq[cc][p];
        }
        __syncthreads();
    }
}

// ---------------------------------------------------------------------------
// z_e = x (straight-through output is numerically x)
// ---------------------------------------------------------------------------
__global__ void vq_ze_kernel(const float* __restrict__ x, float* __restrict__ out_ze) {
    int i = blockIdx.x * blockDim.x + threadIdx.x;   // one float4 each
    const float4* xi = (const float4*)x;
    float4* oi = (float4*)out_ze;
    oi[i] = xi[i];
}

// ---------------------------------------------------------------------------
extern "C" void kernel_launch(void* const* d_in, const int* in_sizes, int n_in,
                              void* d_out, int out_size) {
    const float* x   = (const float*)d_in[0];       // (32,256,32,32) fp32
    const float* emb = (const float*)d_in[1];       // (1024,256) fp32
    float* out_ze = (float*)d_out;                  // first 8388608 floats
    float* out_zq = out_ze + (size_t)NPIX * DD;     // second 8388608 floats

    // prep
    vq_transpose_kernel<<<dim3(KC / 32, DD / 32), dim3(32, 8)>>>(emb);
    vq_hn_kernel<<<KC / 256, 256>>>(emb);

    // distance GEMM + argmax
    vq_main_kernel<<<NPIX / 64, 256>>>(x);

    // outputs
    vq_zq_kernel<<<BB * (HWD / 128), 256>>>(emb, out_zq);
    vq_ze_kernel<<<(NPIX * DD / 4) / 256, 256>>>(x, out_ze);
}

// round 5
// speedup vs baseline: 2.2162x; 2.2162x over previous
#include <cuda_runtime.h>
#include <cuda_bf16.h>
#include <cstdint>

#define KC   1024
#define DD   256
#define BB   32
#define HWD  1024
#define NPIX (BB*HWD)
#define CHW  (DD*HWD)

#define CHUNK_BYTES 8192          // 128 rows x 32 dims bf16
#define STAGE_A     24576         // 3 splits
#define STAGE_BYTES 49152         // A(3) + B(3)

// Scratch (allocation-free __device__ globals)
// g_At: [pixel-tile 256][chunk 8][split 3][8KB]   (48 MB)
// g_Bt: [code-tile 8 ][chunk 8][split 3][8KB]     (1.5 MB)
__device__ __align__(16) unsigned char g_At[(size_t)256 * 8 * 3 * CHUNK_BYTES];
__device__ __align__(16) unsigned char g_Bt[(size_t)8   * 8 * 3 * CHUNK_BYTES];
__device__ float g_hn[KC];
__device__ int   g_argmin[NPIX];

// ---------------------------------------------------------------------------
__device__ __forceinline__ uint32_t smem_u32(const void* p) {
    uint32_t a;
    asm("{ .reg .u64 t; cvta.to.shared.u64 t, %1; cvt.u32.u64 %0, t; }" : "=r"(a) : "l"(p));
    return a;
}
// swizzled byte offset of 16B group g (0..3) in row (0..127); conflict-free ldmatrix
__device__ __host__ __forceinline__ uint32_t swz16(int row, int g) {
    return (uint32_t)((row * 4 + (g ^ ((row >> 1) & 3))) << 4);
}

#define CPASYNC16(d, s) \
    asm volatile("cp.async.cg.shared.global [%0], [%1], 16;" :: "r"(d), "l"(s))
#define CP_COMMIT() asm volatile("cp.async.commit_group;" ::: "memory")
#define CP_WAIT1()  asm volatile("cp.async.wait_group 1;" ::: "memory")
#define CP_WAIT0()  asm volatile("cp.async.wait_group 0;" ::: "memory")

#define LDM4(r, a) \
    asm volatile("ldmatrix.sync.aligned.m8n8.x4.shared.b16 {%0,%1,%2,%3}, [%4];" \
        : "=r"((r)[0]), "=r"((r)[1]), "=r"((r)[2]), "=r"((r)[3]) : "r"(a))

#define MMA16816(c, a, b0, b1) \
    asm volatile("mma.sync.aligned.m16n8k16.row.col.f32.bf16.bf16.f32 " \
        "{%0,%1,%2,%3}, {%4,%5,%6,%7}, {%8,%9}, {%0,%1,%2,%3};" \
        : "+f"((c)[0]), "+f"((c)[1]), "+f"((c)[2]), "+f"((c)[3]) \
        : "r"((a)[0]), "r"((a)[1]), "r"((a)[2]), "r"((a)[3]), "r"(b0), "r"(b1))

// ---------------------------------------------------------------------------
// error-free 3-way bf16 split
__device__ __forceinline__ void split3(float v, __nv_bfloat16& s1,
                                       __nv_bfloat16& s2, __nv_bfloat16& s3) {
    s1 = __float2bfloat16(v);
    float r1 = v - __bfloat162float(s1);
    s2 = __float2bfloat16(r1);
    float r2 = r1 - __bfloat162float(s2);
    s3 = __float2bfloat16(r2);
}

// ---------------------------------------------------------------------------
// Prep X: x (B,C,H,W) fp32 -> swizzled bf16 split tiles.
// grid 2048 = (pixel-tile, chunk); 128 threads; thread = pixel row.
// ---------------------------------------------------------------------------
__global__ __launch_bounds__(128) void vq_prep_x(const float* __restrict__ x) {
    int blk  = blockIdx.x;
    int tile = blk >> 3, ch = blk & 7;
    int b    = tile >> 3, hw0 = (tile & 7) << 7;
    int row  = threadIdx.x;
    const float* xb = x + (size_t)b * CHW + (size_t)(ch * 32) * HWD + hw0 + row;

    unsigned u0[16], u1[16], u2[16];
    #pragma unroll
    for (int i = 0; i < 16; i++) { u0[i] = u1[i] = u2[i] = 0; }
    #pragma unroll
    for (int d = 0; d < 32; d++) {
        float v = xb[(size_t)d * HWD];
        __nv_bfloat16 s1, s2, s3;
        split3(v, s1, s2, s3);
        int idx = d >> 1, sh = (d & 1) * 16;
        u0[idx] |= (unsigned)__bfloat16_as_ushort(s1) << sh;
        u1[idx] |= (unsigned)__bfloat16_as_ushort(s2) << sh;
        u2[idx] |= (unsigned)__bfloat16_as_ushort(s3) << sh;
    }
    unsigned char* base = g_At + (size_t)(tile * 8 + ch) * STAGE_A;
    #pragma unroll
    for (int g = 0; g < 4; g++) {
        uint32_t off = swz16(row, g);
        *(uint4*)(base + off) =
            make_uint4(u0[g*4], u0[g*4+1], u0[g*4+2], u0[g*4+3]);
        *(uint4*)(base + CHUNK_BYTES + off) =
            make_uint4(u1[g*4], u1[g*4+1], u1[g*4+2], u1[g*4+3]);
        *(uint4*)(base + 2*CHUNK_BYTES + off) =
            make_uint4(u2[g*4], u2[g*4+1], u2[g*4+2], u2[g*4+3]);
    }
}

// ---------------------------------------------------------------------------
// Prep E: emb (K,D) fp32 -> swizzled bf16 split tiles.
// grid 64 = (code-tile, chunk); 128 threads; thread = code row.
// ---------------------------------------------------------------------------
__global__ __launch_bounds__(128) void vq_prep_e(const float* __restrict__ emb) {
    int blk = blockIdx.x;
    int nt  = blk >> 3, ch = blk & 7;
    int row = threadIdx.x;
    const float* er = emb + (size_t)(nt * 128 + row) * DD + ch * 32;

    unsigned u0[16], u1[16], u2[16];
    #pragma unroll
    for (int i = 0; i < 16; i++) { u0[i] = u1[i] = u2[i] = 0; }
    #pragma unroll
    for (int d = 0; d < 32; d++) {
        float v = er[d];
        __nv_bfloat16 s1, s2, s3;
        split3(v, s1, s2, s3);
        int idx = d >> 1, sh = (d & 1) * 16;
        u0[idx] |= (unsigned)__bfloat16_as_ushort(s1) << sh;
        u1[idx] |= (unsigned)__bfloat16_as_ushort(s2) << sh;
        u2[idx] |= (unsigned)__bfloat16_as_ushort(s3) << sh;
    }
    unsigned char* base = g_Bt + (size_t)(nt * 8 + ch) * STAGE_A;
    #pragma unroll
    for (int g = 0; g < 4; g++) {
        uint32_t off = swz16(row, g);
        *(uint4*)(base + off) =
            make_uint4(u0[g*4], u0[g*4+1], u0[g*4+2], u0[g*4+3]);
        *(uint4*)(base + CHUNK_BYTES + off) =
            make_uint4(u1[g*4], u1[g*4+1], u1[g*4+2], u1[g*4+3]);
        *(uint4*)(base + 2*CHUNK_BYTES + off) =
            make_uint4(u2[g*4], u2[g*4+1], u2[g*4+2], u2[g*4+3]);
    }
}

// ---------------------------------------------------------------------------
__global__ void vq_hn_kernel(const float* __restrict__ emb) {
    int k = blockIdx.x * blockDim.x + threadIdx.x;
    if (k >= KC) return;
    const float4* row = (const float4*)(emb + (size_t)k * DD);
    float s = 0.f;
    #pragma unroll 8
    for (int i = 0; i < DD / 4; i++) {
        float4 v = row[i];
        s += v.x * v.x + v.y * v.y + v.z * v.z + v.w * v.w;
    }
    g_hn[k] = 0.5f * s;
}

// ---------------------------------------------------------------------------
// Staging: one chunk = A 24KB + B 24KB, linear 16B cp.async (swizzle pre-baked)
// ---------------------------------------------------------------------------
__device__ __forceinline__ void stage_chunk(uint32_t dst,
                                            const unsigned char* Asrc,
                                            const unsigned char* Bsrc, int tid) {
    #pragma unroll
    for (int i = 0; i < 6; i++) {
        uint32_t o = (uint32_t)(tid + i * 256) * 16;
        CPASYNC16(dst + o, Asrc + o);
    }
    #pragma unroll
    for (int i = 0; i < 6; i++) {
        uint32_t o = (uint32_t)(tid + i * 256) * 16;
        CPASYNC16(dst + STAGE_A + o, Bsrc + o);
    }
}

// ---------------------------------------------------------------------------
// Per-chunk compute: 2 k16-steps; load all split frags once, 6 term pairs.
// ---------------------------------------------------------------------------
__device__ __forceinline__ void compute_chunk(uint32_t sb,
                                              const uint32_t offA[4][2],
                                              const uint32_t offB[2][2],
                                              float acc[4][4][4]) {
    #pragma unroll
    for (int ks = 0; ks < 2; ks++) {
        uint32_t Ar[3][4][4], Br[3][2][4];
        #pragma unroll
        for (int s = 0; s < 3; s++) {
            #pragma unroll
            for (int mf = 0; mf < 4; mf++)
                LDM4(Ar[s][mf], sb + s * CHUNK_BYTES + offA[mf][ks]);
            #pragma unroll
            for (int nh = 0; nh < 2; nh++)
                LDM4(Br[s][nh], sb + STAGE_A + s * CHUNK_BYTES + offB[nh][ks]);
        }
        const int SA[6] = {0, 0, 1, 0, 1, 2};
        const int SB[6] = {0, 1, 0, 2, 1, 0};
        #pragma unroll
        for (int t = 0; t < 6; t++) {
            #pragma unroll
            for (int mi = 0; mi < 4; mi++)
                #pragma unroll
                for (int ni = 0; ni < 4; ni++) {
                    uint32_t b0 = Br[SB[t]][ni >> 1][(ni & 1)];
                    uint32_t b1 = Br[SB[t]][ni >> 1][(ni & 1) + 2];
                    MMA16816(acc[mi][ni], Ar[SA[t]][mi], b0, b1);
                }
        }
    }
}

// ---------------------------------------------------------------------------
// Main GEMM + argmax. 256 CTAs x 256 threads. CTA: 128 pixels x 128 codes,
// loop 8 code tiles x 8 k-chunks, bf16x6 split accumulation in fp32.
// ---------------------------------------------------------------------------
__global__ __launch_bounds__(256, 1) void vq_gemm() {
    extern __shared__ __align__(1024) unsigned char dyn[];
    __shared__ float hn_s[KC];
    __shared__ float candS[128][16];
    __shared__ int   candI[128][16];

    int tid  = threadIdx.x;
    int lane = tid & 31, w = tid >> 5;
    int wm   = w & 1, wn = w >> 1;
    int tile = blockIdx.x;
    uint32_t dynb = smem_u32(dyn);

    for (int i = tid; i < KC; i += 256) hn_s[i] = g_hn[i];

    // per-lane ldmatrix offsets (chunk-invariant)
    uint32_t offA[4][2], offB[2][2];
    {
        int rsub = (lane & 7) + ((lane >> 3) & 1) * 8;
        int gsub = lane >> 4;
        #pragma unroll
        for (int mf = 0; mf < 4; mf++)
            #pragma unroll
            for (int ks = 0; ks < 2; ks++)
                offA[mf][ks] = swz16(wm * 64 + mf * 16 + rsub, ks * 2 + gsub);
        #pragma unroll
        for (int nh = 0; nh < 2; nh++)
            #pragma unroll
            for (int ks = 0; ks < 2; ks++)
                offB[nh][ks] = swz16(wn * 32 + nh * 16 + rsub, ks * 2 + gsub);
    }
    __syncthreads();

    const unsigned char* Abase = g_At + (size_t)tile * 8 * STAGE_A;
    float best = -3.0e38f;
    int   bi   = 0;
    float acc[4][4][4];

    for (int nt = 0; nt < 8; nt++) {
        const unsigned char* Bbase = g_Bt + (size_t)nt * 8 * STAGE_A;
        #pragma unroll
        for (int mi = 0; mi < 4; mi++)
            #pragma unroll
            for (int ni = 0; ni < 4; ni++)
                #pragma unroll
                for (int e = 0; e < 4; e++) acc[mi][ni][e] = 0.f;

        stage_chunk(dynb, Abase, Bbase, tid);
        CP_COMMIT();
        for (int c = 0; c < 8; c++) {
            if (c < 7) {
                stage_chunk(dynb + ((c + 1) & 1) * STAGE_BYTES,
                            Abase + (c + 1) * STAGE_A,
                            Bbase + (c + 1) * STAGE_A, tid);
                CP_COMMIT();
                CP_WAIT1();
            } else {
                CP_WAIT0();
            }
            __syncthreads();
            compute_chunk(dynb + (c & 1) * STAGE_BYTES, offA, offB, acc);
            __syncthreads();
        }

        // epilogue: local argmax, smem candidate reduce
        #pragma unroll
        for (int mi = 0; mi < 4; mi++)
            #pragma unroll
            for (int eh = 0; eh < 2; eh++) {
                int p = wm * 64 + mi * 16 + eh * 8 + (lane >> 2);
                float bs = -3.0e38f;
                int   bx = 0;
                #pragma unroll
                for (int ni = 0; ni < 4; ni++)
                    #pragma unroll
                    for (int e2 = 0; e2 < 2; e2++) {
                        int code = nt * 128 + wn * 32 + ni * 8 + (lane & 3) * 2 + e2;
                        float v = acc[mi][ni][eh * 2 + e2] - hn_s[code];
                        if (v > bs) { bs = v; bx = code; }
                    }
                candS[p][wn * 4 + (lane & 3)] = bs;
                candI[p][wn * 4 + (lane & 3)] = bx;
            }
        __syncthreads();
        if (tid < 128) {
            #pragma unroll
            for (int q = 0; q < 16; q++) {
                float s_ = candS[tid][q];
                if (s_ > best) { best = s_; bi = candI[tid][q]; }
            }
        }
        __syncthreads();
    }

    if (tid < 128) g_argmin[tile * 128 + tid] = bi;
}

// ---------------------------------------------------------------------------
// z_q gather: out[b][c][hw] = emb[argmin[b][hw]][c]
// ---------------------------------------------------------------------------
__global__ __launch_bounds__(256) void vq_zq(const float* __restrict__ emb,
                                             float* __restrict__ out) {
    __shared__ int   sidx[64];
    __shared__ float zs[32][65];
    int blk = blockIdx.x;
    int b = blk >> 4, hw0 = (blk & 15) << 6;
    int t = threadIdx.x, lane = t & 31, w = t >> 5;
    if (t < 64) sidx[t] = g_argmin[b * HWD + hw0 + t];
    __syncthreads();
    float* ob = out + (size_t)b * CHW + hw0;
    for (int c0 = 0; c0 < DD; c0 += 32) {
        #pragma unroll
        for (int pp = 0; pp < 8; pp++) {
            int p = w * 8 + pp;
            zs[lane][p] = emb[(size_t)sidx[p] * DD + c0 + lane];
        }
        __syncthreads();
        int p = t & 63, crow = t >> 6;
        #pragma unroll
        for (int i = 0; i < 8; i++) {
            int cc = crow + i * 4;
            ob[(size_t)(c0 + cc) * HWD + p] = zs[cc][p];
        }
        __syncthreads();
    }
}

// ---------------------------------------------------------------------------
__global__ void vq_ze_kernel(const float* __restrict__ x, float* __restrict__ out) {
    int i = blockIdx.x * blockDim.x + threadIdx.x;
    ((float4*)out)[i] = ((const float4*)x)[i];
}

// ---------------------------------------------------------------------------
extern "C" void kernel_launch(void* const* d_in, const int* in_sizes, int n_in,
                              void* d_out, int out_size) {
    const float* x   = (const float*)d_in[0];
    const float* emb = (const float*)d_in[1];
    float* out_ze = (float*)d_out;
    float* out_zq = out_ze + (size_t)NPIX * DD;

    const int dyn_smem = 2 * STAGE_BYTES;   // 98304
    cudaFuncSetAttribute(vq_gemm, cudaFuncAttributeMaxDynamicSharedMemorySize, dyn_smem);

    vq_prep_x<<<2048, 128>>>(x);
    vq_prep_e<<<64, 128>>>(emb);
    vq_hn_kernel<<<KC / 256, 256>>>(emb);
    vq_gemm<<<256, 256, dyn_smem>>>();
    vq_zq<<<512, 256>>>(emb, out_zq);
    vq_ze_kernel<<<(NPIX * DD / 4) / 256, 256>>>(x, out_ze);
}

// round 7
// speedup vs baseline: 5.2764x; 2.3808x over previous
#include <cuda_runtime.h>
#include <cuda_bf16.h>
#include <cstdint>

#define KC   1024
#define DD   256
#define BB   32
#define HWD  1024
#define NPIX (BB*HWD)
#define CHW  (DD*HWD)

#define CHUNK 8192      // 128 rows x 32 dims bf16 tile
#define CAP   16
#define THRESH 1.0f

// Scratch (allocation-free __device__ globals)
__device__ __align__(16) unsigned char g_A1[(size_t)256 * 8 * CHUNK];  // 16MB
__device__ __align__(16) unsigned char g_B1[(size_t)8   * 8 * CHUNK];  // 512KB
__device__ float g_hn[KC];
__device__ int   g_argmin[NPIX];
__device__ __align__(16) unsigned short g_cand[(size_t)NPIX * CAP];
__device__ int   g_cnt[NPIX];

// ---------------------------------------------------------------------------
__device__ __forceinline__ uint32_t smem_u32(const void* p) {
    uint32_t a;
    asm("{ .reg .u64 t; cvta.to.shared.u64 t, %1; cvt.u32.u64 %0, t; }" : "=r"(a) : "l"(p));
    return a;
}
__device__ __forceinline__ uint32_t swz16(int row, int g) {
    return (uint32_t)((row * 4 + (g ^ ((row >> 1) & 3))) << 4);
}

#define CPASYNC16(d, s) \
    asm volatile("cp.async.cg.shared.global [%0], [%1], 16;" :: "r"(d), "l"(s))
#define CP_COMMIT() asm volatile("cp.async.commit_group;" ::: "memory")
#define CP_WAIT1()  asm volatile("cp.async.wait_group 1;" ::: "memory")
#define CP_WAIT0()  asm volatile("cp.async.wait_group 0;" ::: "memory")

#define LDM4(r, a) \
    asm volatile("ldmatrix.sync.aligned.m8n8.x4.shared.b16 {%0,%1,%2,%3}, [%4];" \
        : "=r"((r)[0]), "=r"((r)[1]), "=r"((r)[2]), "=r"((r)[3]) : "r"(a))

#define MMA16816(c, a, b0, b1) \
    asm volatile("mma.sync.aligned.m16n8k16.row.col.f32.bf16.bf16.f32 " \
        "{%0,%1,%2,%3}, {%4,%5,%6,%7}, {%8,%9}, {%0,%1,%2,%3};" \
        : "+f"((c)[0]), "+f"((c)[1]), "+f"((c)[2]), "+f"((c)[3]) \
        : "r"((a)[0]), "r"((a)[1]), "r"((a)[2]), "r"((a)[3]), "r"(b0), "r"(b1))

// ---------------------------------------------------------------------------
// Prep X (+ fused z_e = x): x (B,C,H,W) fp32 -> bf16 swizzled tiles + copy.
// grid 2048 = (pixel-tile, chunk); 128 threads; thread = pixel row.
// ---------------------------------------------------------------------------
__global__ __launch_bounds__(128) void vq_prep_xze(const float* __restrict__ x,
                                                   float* __restrict__ out_ze) {
    int blk  = blockIdx.x;
    int tile = blk >> 3, ch = blk & 7;
    int b    = tile >> 3, hw0 = (tile & 7) << 7;
    int row  = threadIdx.x;
    size_t base_off = (size_t)b * CHW + (size_t)(ch * 32) * HWD + hw0 + row;
    const float* xb = x + base_off;
    float*       zb = out_ze + base_off;

    unsigned u0[16];
    #pragma unroll
    for (int i = 0; i < 16; i++) u0[i] = 0;
    #pragma unroll
    for (int d = 0; d < 32; d++) {
        float v = xb[(size_t)d * HWD];
        zb[(size_t)d * HWD] = v;                       // fused z_e copy
        unsigned h = (unsigned)__bfloat16_as_ushort(__float2bfloat16(v));
        u0[d >> 1] |= h << ((d & 1) * 16);
    }
    unsigned char* base = g_A1 + (size_t)(tile * 8 + ch) * CHUNK;
    #pragma unroll
    for (int g = 0; g < 4; g++)
        *(uint4*)(base + swz16(row, g)) =
            make_uint4(u0[g*4], u0[g*4+1], u0[g*4+2], u0[g*4+3]);
}

// ---------------------------------------------------------------------------
// Prep E: emb (K,D) fp32 -> bf16 swizzled tiles. grid 64 = (nt, chunk).
// ---------------------------------------------------------------------------
__global__ __launch_bounds__(128) void vq_prep_e(const float* __restrict__ emb) {
    int blk = blockIdx.x;
    int nt  = blk >> 3, ch = blk & 7;
    int row = threadIdx.x;
    const float4* er = (const float4*)(emb + (size_t)(nt * 128 + row) * DD + ch * 32);

    unsigned u0[16];
    #pragma unroll
    for (int i = 0; i < 8; i++) {
        float4 v = er[i];
        unsigned a = (unsigned)__bfloat16_as_ushort(__float2bfloat16(v.x));
        unsigned bshort = (unsigned)__bfloat16_as_ushort(__float2bfloat16(v.y));
        unsigned c = (unsigned)__bfloat16_as_ushort(__float2bfloat16(v.z));
        unsigned d = (unsigned)__bfloat16_as_ushort(__float2bfloat16(v.w));
        u0[i*2]   = a | (bshort << 16);
        u0[i*2+1] = c | (d << 16);
    }
    unsigned char* base = g_B1 + (size_t)(nt * 8 + ch) * CHUNK;
    #pragma unroll
    for (int g = 0; g < 4; g++)
        *(uint4*)(base + swz16(row, g)) =
            make_uint4(u0[g*4], u0[g*4+1], u0[g*4+2], u0[g*4+3]);
}

// ---------------------------------------------------------------------------
__global__ void vq_hn_kernel(const float* __restrict__ emb) {
    int k = blockIdx.x * blockDim.x + threadIdx.x;
    if (k >= KC) return;
    const float4* row = (const float4*)(emb + (size_t)k * DD);
    float s = 0.f;
    #pragma unroll 8
    for (int i = 0; i < DD / 4; i++) {
        float4 v = row[i];
        s += v.x * v.x + v.y * v.y + v.z * v.z + v.w * v.w;
    }
    g_hn[k] = 0.5f * s;
}

// ---------------------------------------------------------------------------
// Pass 1: coarse bf16 GEMM + candidate selection.
// 256 CTAs x 256 threads, 2 CTAs/SM. A tile (64KB) resident; B 3-stage ring.
// ---------------------------------------------------------------------------
__global__ __launch_bounds__(256, 2) void vq_pass1() {
    extern __shared__ __align__(1024) unsigned char dyn[];   // A 64KB + ring 24KB
    __shared__ float hn_s[KC];
    __shared__ float candS[128][16];
    __shared__ float pixMax[128];
    __shared__ unsigned short lists[128][CAP];
    __shared__ int cnts[128];

    int tid  = threadIdx.x;
    int lane = tid & 31, w = tid >> 5;
    int wm   = w & 1, wn = w >> 1;
    int tile = blockIdx.x;
    uint32_t dynA = smem_u32(dyn);
    uint32_t ring = dynA + 65536;

    for (int i = tid; i < KC; i += 256) hn_s[i] = g_hn[i];
    if (tid < 128) { pixMax[tid] = -3.0e38f; cnts[tid] = 0; }

    // per-lane ldmatrix offsets (validated layout from R5)
    uint32_t offA[4][2], offB[2][2];
    {
        int rsub = (lane & 7) + ((lane >> 3) & 1) * 8;
        int gsub = lane >> 4;
        #pragma unroll
        for (int mf = 0; mf < 4; mf++)
            #pragma unroll
            for (int ks = 0; ks < 2; ks++)
                offA[mf][ks] = swz16(wm * 64 + mf * 16 + rsub, ks * 2 + gsub);
        #pragma unroll
        for (int nh = 0; nh < 2; nh++)
            #pragma unroll
            for (int ks = 0; ks < 2; ks++)
                offB[nh][ks] = swz16(wn * 32 + nh * 16 + rsub, ks * 2 + gsub);
    }

    // prologue: group0 = whole A tile + B stage 0; group1 = B stage 1
    const unsigned char* Ag = g_A1 + (size_t)tile * 8 * CHUNK;
    #pragma unroll
    for (int i = 0; i < 16; i++) {
        uint32_t o = (uint32_t)(tid + i * 256) * 16;
        CPASYNC16(dynA + o, Ag + o);
    }
    #pragma unroll
    for (int i = 0; i < 2; i++) {
        uint32_t o = (uint32_t)(tid + i * 256) * 16;
        CPASYNC16(ring + o, g_B1 + o);
    }
    CP_COMMIT();
    #pragma unroll
    for (int i = 0; i < 2; i++) {
        uint32_t o = (uint32_t)(tid + i * 256) * 16;
        CPASYNC16(ring + CHUNK + o, g_B1 + CHUNK + o);
    }
    CP_COMMIT();
    __syncthreads();   // smem init visible

    float acc[4][4][4];

    for (int s = 0; s < 64; s++) {
        int ch = s & 7, nt = s >> 3;
        if (s < 62) { CP_WAIT1(); } else { CP_WAIT0(); }
        __syncthreads();
        if (s + 2 < 64) {
            uint32_t dst = ring + ((s + 2) % 3) * CHUNK;
            const unsigned char* src = g_B1 + (size_t)(s + 2) * CHUNK;
            #pragma unroll
            for (int i = 0; i < 2; i++) {
                uint32_t o = (uint32_t)(tid + i * 256) * 16;
                CPASYNC16(dst + o, src + o);
            }
            CP_COMMIT();
        }
        if (ch == 0) {
            #pragma unroll
            for (int mi = 0; mi < 4; mi++)
                #pragma unroll
                for (int ni = 0; ni < 4; ni++)
                    #pragma unroll
                    for (int e = 0; e < 4; e++) acc[mi][ni][e] = 0.f;
        }
        uint32_t sa = dynA + ch * CHUNK;
        uint32_t sb = ring + (s % 3) * CHUNK;
        #pragma unroll
        for (int ks = 0; ks < 2; ks++) {
            uint32_t Ar[4][4], Br[2][4];
            #pragma unroll
            for (int mf = 0; mf < 4; mf++) LDM4(Ar[mf], sa + offA[mf][ks]);
            #pragma unroll
            for (int nh = 0; nh < 2; nh++) LDM4(Br[nh], sb + offB[nh][ks]);
            #pragma unroll
            for (int mi = 0; mi < 4; mi++)
                #pragma unroll
                for (int ni = 0; ni < 4; ni++)
                    MMA16816(acc[mi][ni], Ar[mi],
                             Br[ni >> 1][ni & 1], Br[ni >> 1][(ni & 1) + 2]);
        }

        if (ch == 7) {
            // 1) per-pixel local max
            #pragma unroll
            for (int mi = 0; mi < 4; mi++)
                #pragma unroll
                for (int eh = 0; eh < 2; eh++) {
                    int p = wm * 64 + mi * 16 + eh * 8 + (lane >> 2);
                    float bs = -3.0e38f;
                    #pragma unroll
                    for (int ni = 0; ni < 4; ni++)
                        #pragma unroll
                        for (int e2 = 0; e2 < 2; e2++) {
                            int code = nt * 128 + wn * 32 + ni * 8 + (lane & 3) * 2 + e2;
                            float v = acc[mi][ni][eh * 2 + e2] - hn_s[code];
                            bs = fmaxf(bs, v);
                        }
                    candS[p][wn * 4 + (lane & 3)] = bs;
                }
            __syncthreads();
            // 2) update global running max
            if (tid < 128) {
                float m = pixMax[tid];
                #pragma unroll
                for (int q = 0; q < 16; q++) m = fmaxf(m, candS[tid][q]);
                pixMax[tid] = m;
            }
            __syncthreads();
            // 3) append candidates within THRESH of running max
            #pragma unroll
            for (int mi = 0; mi < 4; mi++)
                #pragma unroll
                for (int eh = 0; eh < 2; eh++) {
                    int p = wm * 64 + mi * 16 + eh * 8 + (lane >> 2);
                    float thr = pixMax[p] - THRESH;
                    #pragma unroll
                    for (int ni = 0; ni < 4; ni++)
                        #pragma unroll
                        for (int e2 = 0; e2 < 2; e2++) {
                            int code = nt * 128 + wn * 32 + ni * 8 + (lane & 3) * 2 + e2;
                            float v = acc[mi][ni][eh * 2 + e2] - hn_s[code];
                            if (v >= thr) {
                                int slot = atomicAdd(&cnts[p], 1);
                                if (slot < CAP) lists[p][slot] = (unsigned short)code;
                            }
                        }
                }
        }
    }

    __syncthreads();
    if (tid < 128) {
        int pix = tile * 128 + tid;
        g_cnt[pix] = cnts[tid];
        uint4* d = (uint4*)(g_cand + (size_t)pix * CAP);
        const uint4* sp = (const uint4*)lists[tid];
        d[0] = sp[0];
        d[1] = sp[1];
    }
}

// ---------------------------------------------------------------------------
// Pass 2: exact fp32 rescore of candidates. Warp per pixel (x4).
// ---------------------------------------------------------------------------
__global__ __launch_bounds__(256) void vq_pass2(const float* __restrict__ x,
                                                const float* __restrict__ emb) {
    int gw   = blockIdx.x * 8 + (threadIdx.x >> 5);
    int lane = threadIdx.x & 31;

    for (int j = 0; j < 4; j++) {
        int pix = gw * 4 + j;
        int b = pix >> 10, hw = pix & 1023;
        const float* xb = x + (size_t)b * CHW + hw;
        float xr[8];
        #pragma unroll
        for (int i = 0; i < 8; i++)
            xr[i] = __ldg(xb + (size_t)(i * 32 + lane) * HWD);

        int cnt = g_cnt[pix];
        float best = -3.0e38f;
        int   bidx = KC;

        if (cnt <= CAP) {
            for (int q = 0; q < cnt; q++) {
                int code = g_cand[(size_t)pix * CAP + q];
                float a = 0.f;
                #pragma unroll
                for (int i = 0; i < 8; i++)
                    a += xr[i] * __ldg(&emb[(size_t)code * DD + i * 32 + lane]);
                #pragma unroll
                for (int off = 16; off; off >>= 1)
                    a += __shfl_xor_sync(0xffffffff, a, off);
                float s = a - __ldg(&g_hn[code]);
                if (s > best || (s == best && code < bidx)) { best = s; bidx = code; }
            }
        } else {
            // overflow fallback: exact rescore of all codes (rare)
            for (int code = 0; code < KC; code++) {
                float a = 0.f;
                #pragma unroll
                for (int i = 0; i < 8; i++)
                    a += xr[i] * __ldg(&emb[(size_t)code * DD + i * 32 + lane]);
                #pragma unroll
                for (int off = 16; off; off >>= 1)
                    a += __shfl_xor_sync(0xffffffff, a, off);
                float s = a - __ldg(&g_hn[code]);
                if (s > best || (s == best && code < bidx)) { best = s; bidx = code; }
            }
        }
        if (lane == 0) g_argmin[pix] = bidx;
    }
}

// ---------------------------------------------------------------------------
// z_q gather: out[b][c][hw] = emb[argmin[b][hw]][c]
// ---------------------------------------------------------------------------
__global__ __launch_bounds__(256) void vq_zq(const float* __restrict__ emb,
                                             float* __restrict__ out) {
    __shared__ int   sidx[64];
    __shared__ float zs[32][65];
    int blk = blockIdx.x;
    int b = blk >> 4, hw0 = (blk & 15) << 6;
    int t = threadIdx.x, lane = t & 31, w = t >> 5;
    if (t < 64) sidx[t] = g_argmin[b * HWD + hw0 + t];
    __syncthreads();
    float* ob = out + (size_t)b * CHW + hw0;
    for (int c0 = 0; c0 < DD; c0 += 32) {
        #pragma unroll
        for (int pp = 0; pp < 8; pp++) {
            int p = w * 8 + pp;
            zs[lane][p] = emb[(size_t)sidx[p] * DD + c0 + lane];
        }
        __syncthreads();
        int p = t & 63, crow = t >> 6;
        #pragma unroll
        for (int i = 0; i < 8; i++) {
            int cc = crow + i * 4;
            ob[(size_t)(c0 + cc) * HWD + p] = zs[cc][p];
        }
        __syncthreads();
    }
}

// ---------------------------------------------------------------------------
extern "C" void kernel_launch(void* const* d_in, const int* in_sizes, int n_in,
                              void* d_out, int out_size) {
    const float* x   = (const float*)d_in[0];
    const float* emb = (const float*)d_in[1];
    float* out_ze = (float*)d_out;
    float* out_zq = out_ze + (size_t)NPIX * DD;

    const int dyn_smem = 65536 + 3 * CHUNK;   // 90112
    cudaFuncSetAttribute(vq_pass1, cudaFuncAttributeMaxDynamicSharedMemorySize, dyn_smem);

    vq_prep_xze<<<2048, 128>>>(x, out_ze);
    vq_prep_e<<<64, 128>>>(emb);
    vq_hn_kernel<<<KC / 256, 256>>>(emb);
    vq_pass1<<<256, 256, dyn_smem>>>();
    vq_pass2<<<1024, 256>>>(x, emb);
    vq_zq<<<512, 256>>>(emb, out_zq);
}